// round 5
// baseline (speedup 1.0000x reference)
#include <cuda_runtime.h>
#include <cstdint>

typedef unsigned long long ull;
typedef unsigned int u32;

#define L 512
#define H 1024
#define C 2

// Scratch
__device__ float g_ap[L * H];      // a_proj + b1, [l][o]
__device__ float g_bp[L * H];      // b_proj,      [l][o]
__device__ float g_f[L * L * C];   // unsymmetrized logits f[i][j][c]

// ---- packed f32x2 helpers ----
__device__ __forceinline__ ull ffma2(ull a, ull b, ull c) {
    ull d;
    asm("fma.rn.f32x2 %0, %1, %2, %3;" : "=l"(d) : "l"(a), "l"(b), "l"(c));
    return d;
}
__device__ __forceinline__ ull fadd2(ull a, ull b) {
    ull d;
    asm("add.rn.f32x2 %0, %1, %2;" : "=l"(d) : "l"(a), "l"(b));
    return d;
}
__device__ __forceinline__ float2 u2f2(ull u) {
    float2 v;
    asm("mov.b64 {%0, %1}, %2;" : "=f"(v.x), "=f"(v.y) : "l"(u));
    return v;
}
__device__ __forceinline__ ull tanh2(ull x) {
    ull r;
    asm("{\n\t"
        ".reg .f32 lo, hi;\n\t"
        "mov.b64 {lo, hi}, %1;\n\t"
        "tanh.approx.f32 lo, lo;\n\t"
        "tanh.approx.f32 hi, hi;\n\t"
        "mov.b64 %0, {lo, hi};\n\t"
        "}" : "=l"(r) : "l"(x));
    return r;
}
__device__ __forceinline__ u32 to_tf32(float f) {
    u32 r;
    asm("cvt.rna.tf32.f32 %0, %1;" : "=r"(r) : "f"(f));
    return r;
}
__device__ __forceinline__ void mma_tf32(float c[4], u32 a0, u32 a1, u32 a2, u32 a3,
                                         u32 b0, u32 b1) {
    asm("mma.sync.aligned.m16n8k8.row.col.f32.tf32.tf32.f32 "
        "{%0,%1,%2,%3}, {%4,%5,%6,%7}, {%8,%9}, {%0,%1,%2,%3};"
        : "+f"(c[0]), "+f"(c[1]), "+f"(c[2]), "+f"(c[3])
        : "r"(a0), "r"(a1), "r"(a2), "r"(a3), "r"(b0), "r"(b1));
}

// ============================================================
// Kernel 1: tf32 MMA GEMM. 128-thread CTAs, tile 32l x 32o,
// BOTH ap/bp outputs. grid 512 (=3.5 waves). Row-major pad-36
// smem (conflict-free frag LDS + conflict-free STS.128 fills),
// double buffered, 1 syncthreads per 32-k block.
// ============================================================
#define G_BM 32
#define G_BN 32
#define G_KC 32
#define G_PAD 36

__global__ __launch_bounds__(128) void k1_mma(const float* __restrict__ x,
                                              const float* __restrict__ W1,
                                              const float* __restrict__ b1) {
    __shared__ __align__(16) float xs[2][G_BM][G_PAD];
    __shared__ __align__(16) float was[2][G_BN][G_PAD];
    __shared__ __align__(16) float wbs[2][G_BN][G_PAD];

    const int t = threadIdx.x;
    const int lane = t & 31;
    const int wid = t >> 5;
    const int gid = lane >> 2;
    const int tig = lane & 3;
    const int wm = wid & 1;        // 2 m-halves (16 rows each)
    const int wn = wid >> 1;       // 2 n-halves (16 cols each)
    const int lblk = blockIdx.y * G_BM;
    const int oblk = blockIdx.x * G_BN;

    // loader: row r (0..31), k chunks c4 = (t&3)*8 + {0,4}
    const int r = t >> 2;
    const int c40 = (t & 3) * 8;

    const float* xp = x + (lblk + r) * H + c40;
    const float* wp = W1 + (oblk + r) * (2 * H) + c40;

    float accA[2][4], accB[2][4];
#pragma unroll
    for (int na = 0; na < 2; na++)
#pragma unroll
        for (int q = 0; q < 4; q++) { accA[na][q] = 0.f; accB[na][q] = 0.f; }

    float4 rx[2], rwa[2], rwb[2];

#define LOAD_GLB(kb)                                   \
    do {                                               \
        rx[0]  = *(const float4*)(xp + (kb));          \
        rx[1]  = *(const float4*)(xp + (kb) + 4);      \
        rwa[0] = *(const float4*)(wp + (kb));          \
        rwa[1] = *(const float4*)(wp + (kb) + 4);      \
        rwb[0] = *(const float4*)(wp + (kb) + H);      \
        rwb[1] = *(const float4*)(wp + (kb) + H + 4);  \
    } while (0)

#define STORE_TILES(bf)                                                  \
    do {                                                                 \
        _Pragma("unroll")                                                \
        for (int q = 0; q < 2; q++) {                                    \
            const int c4 = c40 + q * 4;                                  \
            uint4 v;                                                     \
            v.x = to_tf32(rx[q].x);  v.y = to_tf32(rx[q].y);             \
            v.z = to_tf32(rx[q].z);  v.w = to_tf32(rx[q].w);             \
            *(uint4*)&xs[bf][r][c4] = v;                                 \
            v.x = to_tf32(rwa[q].x); v.y = to_tf32(rwa[q].y);            \
            v.z = to_tf32(rwa[q].z); v.w = to_tf32(rwa[q].w);            \
            *(uint4*)&was[bf][r][c4] = v;                                \
            v.x = to_tf32(rwb[q].x); v.y = to_tf32(rwb[q].y);            \
            v.z = to_tf32(rwb[q].z); v.w = to_tf32(rwb[q].w);            \
            *(uint4*)&wbs[bf][r][c4] = v;                                \
        }                                                                \
    } while (0)

#define COMPUTE(bf)                                                      \
    do {                                                                 \
        _Pragma("unroll")                                                \
        for (int ks = 0; ks < 4; ks++) {                                 \
            const int k0 = ks * 8;                                       \
            const int ra0 = wm * 16 + gid;                               \
            u32 a0 = *(const u32*)&xs[bf][ra0][k0 + tig];                \
            u32 a1 = *(const u32*)&xs[bf][ra0 + 8][k0 + tig];            \
            u32 a2 = *(const u32*)&xs[bf][ra0][k0 + tig + 4];            \
            u32 a3 = *(const u32*)&xs[bf][ra0 + 8][k0 + tig + 4];        \
            _Pragma("unroll")                                            \
            for (int na = 0; na < 2; na++) {                             \
                const int rn = wn * 16 + na * 8 + gid;                   \
                u32 ba0 = *(const u32*)&was[bf][rn][k0 + tig];           \
                u32 ba1 = *(const u32*)&was[bf][rn][k0 + tig + 4];       \
                u32 bb0 = *(const u32*)&wbs[bf][rn][k0 + tig];           \
                u32 bb1 = *(const u32*)&wbs[bf][rn][k0 + tig + 4];       \
                mma_tf32(accA[na], a0, a1, a2, a3, ba0, ba1);            \
                mma_tf32(accB[na], a0, a1, a2, a3, bb0, bb1);            \
            }                                                            \
        }                                                                \
    } while (0)

    LOAD_GLB(0);
    STORE_TILES(0);
    __syncthreads();

    int buf = 0;
#pragma unroll 1
    for (int it = 0; it < H / G_KC; it++) {
        if (it < H / G_KC - 1) LOAD_GLB((it + 1) * G_KC);
        COMPUTE(buf);
        if (it < H / G_KC - 1) {
            STORE_TILES(buf ^ 1);
            __syncthreads();
            buf ^= 1;
        }
    }

    // epilogue: c0=(g,2t) c1=(g,2t+1) c2=(g+8,2t) c3=(g+8,2t+1)
    const int row0 = lblk + wm * 16 + gid;
#pragma unroll
    for (int na = 0; na < 2; na++) {
        const int col = oblk + wn * 16 + na * 8 + tig * 2;
        const float2 bv = *(const float2*)&b1[col];
        float2 v;
        v.x = accA[na][0] + bv.x; v.y = accA[na][1] + bv.y;
        *(float2*)&g_ap[row0 * H + col] = v;
        v.x = accA[na][2] + bv.x; v.y = accA[na][3] + bv.y;
        *(float2*)&g_ap[(row0 + 8) * H + col] = v;
        v.x = accB[na][0]; v.y = accB[na][1];
        *(float2*)&g_bp[row0 * H + col] = v;
        v.x = accB[na][2]; v.y = accB[na][3];
        *(float2*)&g_bp[(row0 + 8) * H + col] = v;
    }
#undef LOAD_GLB
#undef STORE_TILES
#undef COMPUTE
}

// ============================================================
// Kernel 2: f[i,j,c] = sum_h tanh(ap[j,h] + bp[i,h]) * W2[c,h]
// Tile 16i x 32j, 256 threads, HC=128, register prefetch of the
// next tile overlapped with compute. MUFU-bound.
// ============================================================
#define P_TI 16
#define P_TJ 32
#define P_HC 128
#define P_PAD 130

__global__ __launch_bounds__(256) void k2_pair(const float* __restrict__ W2) {
    __shared__ __align__(16) float as[P_TJ][P_PAD];   // ap rows (j)
    __shared__ __align__(16) float bs[P_TI][P_PAD];   // bp rows (i)
    __shared__ __align__(16) float w2s[2][P_HC];

    const int t = threadIdx.x;
    const int tx = t & 15;   // j
    const int ty = t >> 4;   // i (16 values)
    const int jblk = blockIdx.x * P_TJ;
    const int iblk = blockIdx.y * P_TI;

    ull acc[2][2];
    acc[0][0] = acc[0][1] = acc[1][0] = acc[1][1] = 0ull;

    float2 ra[8], rb[4], rw;
    // loader index maps
    const int lar = t >> 6, lac = (t & 63) * 2;     // +q*4 rows for as (32 rows)
    const int wr = t >> 6, wc = (t & 63) * 2;       // w2 (t<128)

#define LDG_BLOCK(hb)                                                         \
    do {                                                                      \
        _Pragma("unroll")                                                     \
        for (int q = 0; q < 8; q++)                                           \
            ra[q] = *(const float2*)&g_ap[(jblk + lar + q * 4) * H + (hb) + lac]; \
        _Pragma("unroll")                                                     \
        for (int q = 0; q < 4; q++)                                           \
            rb[q] = *(const float2*)&g_bp[(iblk + lar + q * 4) * H + (hb) + lac]; \
        if (t < 128) rw = *(const float2*)&W2[wr * H + (hb) + wc];            \
    } while (0)

#define STORE_BLOCK()                                                         \
    do {                                                                      \
        _Pragma("unroll")                                                     \
        for (int q = 0; q < 8; q++) *(float2*)&as[lar + q * 4][lac] = ra[q];  \
        _Pragma("unroll")                                                     \
        for (int q = 0; q < 4; q++) *(float2*)&bs[lar + q * 4][lac] = rb[q];  \
        if (t < 128) *(float2*)&w2s[wr][wc] = rw;                             \
    } while (0)

    LDG_BLOCK(0);

    for (int hb = 0; hb < H; hb += P_HC) {
        STORE_BLOCK();
        __syncthreads();
        if (hb + P_HC < H) LDG_BLOCK(hb + P_HC);

#pragma unroll 16
        for (int hp = 0; hp < P_HC / 2; hp++) {
            ull a0 = *(const ull*)&as[tx][hp * 2];
            ull a1 = *(const ull*)&as[tx + 16][hp * 2];
            ull b0 = *(const ull*)&bs[ty][hp * 2];
            ull w0 = *(const ull*)&w2s[0][hp * 2];
            ull w1 = *(const ull*)&w2s[1][hp * 2];

            ull t0 = tanh2(fadd2(a0, b0));
            ull t1 = tanh2(fadd2(a1, b0));

            acc[0][0] = ffma2(t0, w0, acc[0][0]);
            acc[0][1] = ffma2(t0, w1, acc[0][1]);
            acc[1][0] = ffma2(t1, w0, acc[1][0]);
            acc[1][1] = ffma2(t1, w1, acc[1][1]);
        }
        __syncthreads();
    }

    const int i = iblk + ty;
#pragma unroll
    for (int jv = 0; jv < 2; jv++) {
        const int j = jblk + tx + jv * 16;
        float2 s0 = u2f2(acc[jv][0]);
        float2 s1 = u2f2(acc[jv][1]);
        float2 o;
        o.x = s0.x + s0.y;
        o.y = s1.x + s1.y;
        *(float2*)&g_f[(i * L + j) * 2] = o;
    }
#undef LDG_BLOCK
#undef STORE_BLOCK
}

// ============================================================
// Kernel 3: out[i,j,c] = 0.5*(f[i,j,c] + f[j,i,c]) + b2[c]
// ============================================================
__global__ __launch_bounds__(256) void k3_sym(const float* __restrict__ b2,
                                              float* __restrict__ out) {
    const int idx = blockIdx.x * 256 + threadIdx.x;
    const int i = idx >> 9;
    const int j = idx & (L - 1);
    const float2 fij = *(const float2*)&g_f[idx * 2];
    const float2 fji = *(const float2*)&g_f[((j << 9) | i) * 2];
    float2 r;
    r.x = (fij.x + fji.x) * 0.5f + b2[0];
    r.y = (fij.y + fji.y) * 0.5f + b2[1];
    *(float2*)&out[idx * 2] = r;
}

extern "C" void kernel_launch(void* const* d_in, const int* in_sizes, int n_in,
                              void* d_out, int out_size) {
    const float* x  = (const float*)d_in[0];
    const float* W1 = (const float*)d_in[1];
    const float* b1 = (const float*)d_in[2];
    const float* W2 = (const float*)d_in[3];
    const float* b2 = (const float*)d_in[4];
    float* out = (float*)d_out;

    k1_mma<<<dim3(H / G_BN, L / G_BM), 128>>>(x, W1, b1);
    k2_pair<<<dim3(L / P_TJ, L / P_TI), 256>>>(W2);
    k3_sym<<<(L * L) / 256, 256>>>(b2, out);
}